// round 4
// baseline (speedup 1.0000x reference)
#include <cuda_runtime.h>
#include <math.h>

// Problem constants (match reference)
#define T      512
#define HDIM   2048
#define NE     32
#define TOPK   8
#define IDIM   1408
#define NGRP   8
#define TKG    4
#define CAP    256          // 2*T*K/E
#define RSF    2.5f
#define ISH    2816         // I * NS (shared experts intermediate)

// ---------------- device scratch (static; no allocations) ----------------
__device__ int   g_topk_ids[T * TOPK];
__device__ float g_topk_w[T * TOPK];
__device__ int   g_assign_slot[T * TOPK];
__device__ int   g_slot_token[NE * CAP];
__device__ int   g_counts[NE];
__device__ float g_h1[NE * CAP * IDIM];
__device__ float g_y [NE * CAP * HDIM];
__device__ float g_hs[T * ISH];

#define PTR_PARAM 0
#define PTR_H1    1
#define PTR_Y     2
#define PTR_HS    3

template <int M>
__device__ __forceinline__ float* resolve(float* p) {
    if constexpr (M == PTR_H1) return g_h1;
    else if constexpr (M == PTR_Y) return g_y;
    else if constexpr (M == PTR_HS) return g_hs;
    else return p;
}

// ---------------- tf32 helpers ----------------
__device__ __forceinline__ unsigned f2tf(float f) {
    unsigned r; asm("cvt.rna.tf32.f32 %0, %1;" : "=r"(r) : "f"(f)); return r;
}
__device__ __forceinline__ void mma_tf32(float* c, uint4 a, uint2 b) {
    asm("mma.sync.aligned.m16n8k8.row.col.f32.tf32.tf32.f32 "
        "{%0,%1,%2,%3},{%4,%5,%6,%7},{%8,%9},{%0,%1,%2,%3};"
        : "+f"(c[0]), "+f"(c[1]), "+f"(c[2]), "+f"(c[3])
        : "r"(a.x), "r"(a.y), "r"(a.z), "r"(a.w), "r"(b.x), "r"(b.y));
}
__device__ __forceinline__ float silu_mul(float g, float u) {
    return (g / (1.f + expf(-g))) * u;
}

// Fragment-major staging. A element (m,k) within a [128 x 16] stage block:
//   lane = (m&7)*4 + (k&3),  reg = ((m>>3)&1) + 2*((k>>2)&1)
//   stored at Af[k>>3][m>>4][lane].reg
// B element (k,n) within a [16 x N] stage block:
//   lane = (n&7)*4 + (k&3),  reg = (k>>2)&1
//   stored at Bf[k>>3][n>>3][lane].reg
__device__ __forceinline__ void stageA(unsigned* dst, int m, int k4, float4 v) {
    int k_tile = k4 >> 3;
    int m_tile = m >> 4;
    int reg    = ((m >> 3) & 1) + ((k4 >> 2) & 1) * 2;
    int lane0  = (m & 7) * 4;
    unsigned* p = dst + ((k_tile * 8 + m_tile) * 32 + lane0) * 4 + reg;
    p[0] = f2tf(v.x); p[4] = f2tf(v.y); p[8] = f2tf(v.z); p[12] = f2tf(v.w);
}
__device__ __forceinline__ void stageB(unsigned* dst, int NT, int k, int n4, float4 v) {
    int k_tile = k >> 3;
    int n_tile = n4 >> 3;
    int reg    = (k >> 2) & 1;
    int lane0  = (n4 & 7) * 4 + (k & 3);
    unsigned* p = dst + ((k_tile * NT + n_tile) * 32 + lane0) * 2 + reg;
    p[0] = f2tf(v.x); p[8] = f2tf(v.y); p[16] = f2tf(v.z); p[24] = f2tf(v.w);
}

// ---------------- routing: noaux_tc grouped top-k ----------------
__global__ void routing_kernel(const float* __restrict__ x,
                               const float* __restrict__ gw,
                               const float* __restrict__ bias) {
    int t    = blockIdx.x;
    int tid  = threadIdx.x;
    int lane = tid & 31;
    int wid  = tid >> 5;

    __shared__ float part[8][32];
    const float* xr = x + (long long)t * HDIM;
    float acc = 0.f;
    int h0 = wid * (HDIM / 8);
    for (int h = h0; h < h0 + HDIM / 8; ++h)
        acc += xr[h] * gw[h * NE + lane];
    part[wid][lane] = acc;
    __syncthreads();

    if (wid != 0) return;

    float logit = 0.f;
#pragma unroll
    for (int w = 0; w < 8; ++w) logit += part[w][lane];

    float s  = 1.f / (1.f + expf(-logit));
    float sb = s + bias[lane];

    float p   = __shfl_xor_sync(0xffffffffu, sb, 1);
    float hi  = fmaxf(sb, p), lo = fminf(sb, p);
    float hi2 = __shfl_xor_sync(0xffffffffu, hi, 2);
    float lo2 = __shfl_xor_sync(0xffffffffu, lo, 2);
    float gs  = (hi >= hi2) ? hi + fmaxf(hi2, lo) : hi2 + fmaxf(hi, lo2);

    int g = lane >> 2;
    int grank = 0;
#pragma unroll
    for (int g2 = 0; g2 < NGRP; ++g2) {
        float og = __shfl_sync(0xffffffffu, gs, g2 * 4);
        if (og > gs || (og == gs && g2 < g)) ++grank;
    }
    float cand = (grank < TKG) ? sb : -INFINITY;

    float v = cand;
    int   sel_e = 0; float sel_w = 0.f;
#pragma unroll
    for (int k = 0; k < TOPK; ++k) {
        float bv = v; int bi = lane;
#pragma unroll
        for (int off = 16; off; off >>= 1) {
            float ov = __shfl_xor_sync(0xffffffffu, bv, off);
            int   oi = __shfl_xor_sync(0xffffffffu, bi, off);
            if (ov > bv || (ov == bv && oi < bi)) { bv = ov; bi = oi; }
        }
        float ws = __shfl_sync(0xffffffffu, s, bi);
        if (lane == k)  { sel_e = bi; sel_w = ws; }
        if (lane == bi) v = -INFINITY;
    }

    float wv = (lane < TOPK) ? sel_w : 0.f;
#pragma unroll
    for (int off = 16; off; off >>= 1) wv += __shfl_xor_sync(0xffffffffu, wv, off);
    if (lane < TOPK) {
        g_topk_ids[t * TOPK + lane] = sel_e;
        g_topk_w  [t * TOPK + lane] = sel_w / wv * RSF;
    }
}

// ---------------- deterministic capacity ranking ----------------
__global__ void rank_kernel() {
    int w    = threadIdx.x >> 5;
    int lane = threadIdx.x & 31;
    int cnt  = 0;
    for (int i0 = 0; i0 < T * TOPK; i0 += 32) {
        int i = i0 + lane;
        int e = g_topk_ids[i];
        bool m = (e == w);
        unsigned mask = __ballot_sync(0xffffffffu, m);
        if (m) {
            int r = cnt + __popc(mask & ((1u << lane) - 1u));
            if (r < CAP) {
                g_assign_slot[i] = w * CAP + r;
                g_slot_token[w * CAP + r] = i >> 3;
            } else {
                g_assign_slot[i] = -1;
            }
        }
        cnt += __popc(mask);
    }
    if (lane == 0) g_counts[w] = min(cnt, CAP);
}

// ============================================================================
// Fused gate/up tf32 GEMM: C = silu(A@Bg)*(A@Bu). Block M=128,N=64.
// 8 warps 4(m) x 2(n); warp tile 32x32. Fragment-major SMEM, double-buffered.
// ============================================================================
template <bool GATHER, bool GROUPED, int AM, int CM>
__global__ void __launch_bounds__(256, 2)
gemm_fused(const float* __restrict__ Ain, int lda,
           const float* __restrict__ B, int ldb, int up_off, long long b_estride,
           float* __restrict__ Cin, int ldc, long long c_estride,
           int M, int Kd) {
    const float* A  = resolve<AM>(const_cast<float*>(Ain));
    float*       Cm = resolve<CM>(Cin);

    const int e    = GROUPED ? blockIdx.z : 0;
    const int Mloc = GROUPED ? g_counts[e] : M;
    const int m0   = blockIdx.y * 128;
    if (m0 >= Mloc) return;
    const int n0   = blockIdx.x * 64;

    const float* Bp = B + (GROUPED ? (long long)e * b_estride : 0ll);
    float*       Cp = Cm + (GROUPED ? (long long)e * c_estride : 0ll);

    // [stage][k_tile][m_tile|n_tile][lane]
    __shared__ uint4 Af[2][2][8][32];    // 16 KB
    __shared__ uint2 Bgf[2][2][8][32];   //  8 KB
    __shared__ uint2 Buf[2][2][8][32];   //  8 KB

    const int tid  = threadIdx.x;
    const int lane = tid & 31;
    const int wid  = tid >> 5;
    const int gid  = lane >> 2;
    const int tig  = lane & 3;
    const int mt0  = (wid >> 1) * 2;     // first m16 tile of warp
    const int nt0  = (wid & 1) * 4;      // first n8 tile of warp

    // A gmem mapping: rows r0, r0+64; k-quad k4
    const int r0 = tid >> 2;
    const int k4 = (tid & 3) * 4;
    const int gm0 = m0 + r0, gm1 = m0 + r0 + 64;
    const bool av0 = gm0 < Mloc, av1 = gm1 < Mloc;
    int row0, row1;
    if (GATHER) {
        row0 = av0 ? g_slot_token[e * CAP + gm0] : 0;
        row1 = av1 ? g_slot_token[e * CAP + gm1] : 0;
    } else {
        row0 = av0 ? gm0 : 0;
        row1 = av1 ? gm1 : 0;
    }
    const float* ap0 = A + (long long)row0 * lda + k4;
    const float* ap1 = A + (long long)row1 * lda + k4;

    // B gmem mapping: row bk (one of 16), 4 cols bn4
    const int bk  = tid >> 4;
    const int bn4 = (tid & 15) * 4;
    const float* bgp = Bp + (long long)bk * ldb + n0 + bn4;
    const float* bup = bgp + up_off;

    float accg[2][4][4], accu[2][4][4];
#pragma unroll
    for (int mi = 0; mi < 2; ++mi)
#pragma unroll
        for (int ni = 0; ni < 4; ++ni)
#pragma unroll
            for (int r = 0; r < 4; ++r) { accg[mi][ni][r] = 0.f; accu[mi][ni][r] = 0.f; }

    const float4 fz = make_float4(0.f, 0.f, 0.f, 0.f);
    float4 ra0 = av0 ? *(const float4*)(ap0) : fz;
    float4 ra1 = av1 ? *(const float4*)(ap1) : fz;
    float4 rbg = *(const float4*)(bgp);
    float4 rbu = *(const float4*)(bup);

    // prologue stage 0
    stageA((unsigned*)&Af[0][0][0][0], r0,      k4, ra0);
    stageA((unsigned*)&Af[0][0][0][0], r0 + 64, k4, ra1);
    stageB((unsigned*)&Bgf[0][0][0][0], 8, bk, bn4, rbg);
    stageB((unsigned*)&Buf[0][0][0][0], 8, bk, bn4, rbu);
    __syncthreads();

    for (int k0 = 0; k0 < Kd; k0 += 16) {
        const int st = (k0 >> 4) & 1;
        const bool nxt = (k0 + 16) < Kd;
        if (nxt) {
            ra0 = av0 ? *(const float4*)(ap0 + k0 + 16) : fz;
            ra1 = av1 ? *(const float4*)(ap1 + k0 + 16) : fz;
            rbg = *(const float4*)(bgp + (long long)(k0 + 16) * ldb);
            rbu = *(const float4*)(bup + (long long)(k0 + 16) * ldb);
        }
#pragma unroll
        for (int kt = 0; kt < 2; ++kt) {
            uint4 af[2];
            uint2 bgr[4], bur[4];
#pragma unroll
            for (int mi = 0; mi < 2; ++mi) af[mi] = Af[st][kt][mt0 + mi][lane];
#pragma unroll
            for (int ni = 0; ni < 4; ++ni) {
                bgr[ni] = Bgf[st][kt][nt0 + ni][lane];
                bur[ni] = Buf[st][kt][nt0 + ni][lane];
            }
#pragma unroll
            for (int ni = 0; ni < 4; ++ni)
#pragma unroll
                for (int mi = 0; mi < 2; ++mi) {
                    mma_tf32(accg[mi][ni], af[mi], bgr[ni]);
                    mma_tf32(accu[mi][ni], af[mi], bur[ni]);
                }
        }
        if (nxt) {
            stageA((unsigned*)&Af[st ^ 1][0][0][0], r0,      k4, ra0);
            stageA((unsigned*)&Af[st ^ 1][0][0][0], r0 + 64, k4, ra1);
            stageB((unsigned*)&Bgf[st ^ 1][0][0][0], 8, bk, bn4, rbg);
            stageB((unsigned*)&Buf[st ^ 1][0][0][0], 8, bk, bn4, rbu);
        }
        __syncthreads();
    }

    // epilogue
#pragma unroll
    for (int mi = 0; mi < 2; ++mi) {
        int rA = m0 + (mt0 + mi) * 16 + gid;
        int rB = rA + 8;
#pragma unroll
        for (int ni = 0; ni < 4; ++ni) {
            int c0 = n0 + (nt0 + ni) * 8 + 2 * tig;
            if (rA < Mloc) {
                Cp[(long long)rA * ldc + c0    ] = silu_mul(accg[mi][ni][0], accu[mi][ni][0]);
                Cp[(long long)rA * ldc + c0 + 1] = silu_mul(accg[mi][ni][1], accu[mi][ni][1]);
            }
            if (rB < Mloc) {
                Cp[(long long)rB * ldc + c0    ] = silu_mul(accg[mi][ni][2], accu[mi][ni][2]);
                Cp[(long long)rB * ldc + c0 + 1] = silu_mul(accg[mi][ni][3], accu[mi][ni][3]);
            }
        }
    }
}

// ============================================================================
// Plain tf32 GEMM: C = A @ B. Block M=128,N=128. 8 warps 2(m) x 4(n);
// warp tile 64x32. Fragment-major SMEM, double-buffered.
// ============================================================================
template <bool GROUPED, int AM, int CM>
__global__ void __launch_bounds__(256, 2)
gemm_plain(const float* __restrict__ Ain, int lda, long long a_estride,
           const float* __restrict__ B, int ldb, long long b_estride,
           float* __restrict__ Cin, int ldc, long long c_estride,
           int M, int Kd) {
    const float* A  = resolve<AM>(const_cast<float*>(Ain));
    float*       Cm = resolve<CM>(Cin);

    const int e    = GROUPED ? blockIdx.z : 0;
    const int Mloc = GROUPED ? g_counts[e] : M;
    const int m0   = blockIdx.y * 128;
    if (m0 >= Mloc) return;
    const int n0   = blockIdx.x * 128;

    const float* Bp = B + (GROUPED ? (long long)e * b_estride : 0ll);
    const float* Ap = A + (GROUPED ? (long long)e * a_estride : 0ll);
    float*       Cp = Cm + (GROUPED ? (long long)e * c_estride : 0ll);

    __shared__ uint4 Af[2][2][8][32];    // 16 KB
    __shared__ uint2 Bf[2][2][16][32];   // 16 KB

    const int tid  = threadIdx.x;
    const int lane = tid & 31;
    const int wid  = tid >> 5;
    const int gid  = lane >> 2;
    const int tig  = lane & 3;
    const int mt0  = (wid >> 2) * 4;     // first m16 tile (4 per warp)
    const int nt0  = (wid & 3) * 4;      // first n8 tile (4 per warp)

    const int r0 = tid >> 2;
    const int k4 = (tid & 3) * 4;
    const int gm0 = m0 + r0, gm1 = m0 + r0 + 64;
    const bool av0 = gm0 < Mloc, av1 = gm1 < Mloc;
    const float* ap0 = Ap + (long long)(av0 ? gm0 : 0) * lda + k4;
    const float* ap1 = Ap + (long long)(av1 ? gm1 : 0) * lda + k4;

    const int bk  = tid >> 5;            // rows bk, bk+8
    const int bn4 = (tid & 31) * 4;
    const float* bp0 = Bp + (long long)bk * ldb + n0 + bn4;
    const float* bp1 = bp0 + 8ll * ldb;

    float acc[4][4][4];
#pragma unroll
    for (int mi = 0; mi < 4; ++mi)
#pragma unroll
        for (int ni = 0; ni < 4; ++ni)
#pragma unroll
            for (int r = 0; r < 4; ++r) acc[mi][ni][r] = 0.f;

    const float4 fz = make_float4(0.f, 0.f, 0.f, 0.f);
    float4 ra0 = av0 ? *(const float4*)(ap0) : fz;
    float4 ra1 = av1 ? *(const float4*)(ap1) : fz;
    float4 rb0 = *(const float4*)(bp0);
    float4 rb1 = *(const float4*)(bp1);

    stageA((unsigned*)&Af[0][0][0][0], r0,      k4, ra0);
    stageA((unsigned*)&Af[0][0][0][0], r0 + 64, k4, ra1);
    stageB((unsigned*)&Bf[0][0][0][0], 16, bk,     bn4, rb0);
    stageB((unsigned*)&Bf[0][0][0][0], 16, bk + 8, bn4, rb1);
    __syncthreads();

    for (int k0 = 0; k0 < Kd; k0 += 16) {
        const int st = (k0 >> 4) & 1;
        const bool nxt = (k0 + 16) < Kd;
        if (nxt) {
            ra0 = av0 ? *(const float4*)(ap0 + k0 + 16) : fz;
            ra1 = av1 ? *(const float4*)(ap1 + k0 + 16) : fz;
            rb0 = *(const float4*)(bp0 + (long long)(k0 + 16) * ldb);
            rb1 = *(const float4*)(bp1 + (long long)(k0 + 16) * ldb);
        }
#pragma unroll
        for (int kt = 0; kt < 2; ++kt) {
            uint4 af[4];
            uint2 bf[4];
#pragma unroll
            for (int mi = 0; mi < 4; ++mi) af[mi] = Af[st][kt][mt0 + mi][lane];
#pragma unroll
            for (int ni = 0; ni < 4; ++ni) bf[ni] = Bf[st][kt][nt0 + ni][lane];
#pragma unroll
            for (int ni = 0; ni < 4; ++ni)
#pragma unroll
                for (int mi = 0; mi < 4; ++mi)
                    mma_tf32(acc[mi][ni], af[mi], bf[ni]);
        }
        if (nxt) {
            stageA((unsigned*)&Af[st ^ 1][0][0][0], r0,      k4, ra0);
            stageA((unsigned*)&Af[st ^ 1][0][0][0], r0 + 64, k4, ra1);
            stageB((unsigned*)&Bf[st ^ 1][0][0][0], 16, bk,     bn4, rb0);
            stageB((unsigned*)&Bf[st ^ 1][0][0][0], 16, bk + 8, bn4, rb1);
        }
        __syncthreads();
    }

#pragma unroll
    for (int mi = 0; mi < 4; ++mi) {
        int rA = m0 + (mt0 + mi) * 16 + gid;
        int rB = rA + 8;
#pragma unroll
        for (int ni = 0; ni < 4; ++ni) {
            int c0 = n0 + (nt0 + ni) * 8 + 2 * tig;
            if (rA < Mloc) {
                Cp[(long long)rA * ldc + c0    ] = acc[mi][ni][0];
                Cp[(long long)rA * ldc + c0 + 1] = acc[mi][ni][1];
            }
            if (rB < Mloc) {
                Cp[(long long)rB * ldc + c0    ] = acc[mi][ni][2];
                Cp[(long long)rB * ldc + c0 + 1] = acc[mi][ni][3];
            }
        }
    }
}

// ---------------- combine ----------------
__global__ void combine_kernel(float* __restrict__ out) {
    int t = blockIdx.x;
    __shared__ int   sslot[TOPK];
    __shared__ float sw[TOPK];
    if (threadIdx.x < TOPK) {
        sslot[threadIdx.x] = g_assign_slot[t * TOPK + threadIdx.x];
        sw[threadIdx.x]    = g_topk_w[t * TOPK + threadIdx.x];
    }
    __syncthreads();
    for (int h = threadIdx.x; h < HDIM; h += 256) {
        float acc = out[(long long)t * HDIM + h];
#pragma unroll
        for (int k = 0; k < TOPK; ++k) {
            int sl = sslot[k];
            if (sl >= 0) acc += sw[k] * g_y[(long long)sl * HDIM + h];
        }
        out[(long long)t * HDIM + h] = acc;
    }
}

// ---------------- launch ----------------
extern "C" void kernel_launch(void* const* d_in, const int* in_sizes, int n_in,
                              void* d_out, int out_size) {
    const float* x     = (const float*)d_in[0];
    const float* gw    = (const float*)d_in[2];
    const float* bias  = (const float*)d_in[3];
    const float* w13   = (const float*)d_in[4];
    const float* w2    = (const float*)d_in[5];
    const float* sgu   = (const float*)d_in[6];
    const float* sdn   = (const float*)d_in[7];
    float* out = (float*)d_out;

    routing_kernel<<<T, 256>>>(x, gw, bias);
    rank_kernel<<<1, 1024>>>();
    // routed gemm1: gathered X @ w13 (fused silu*up) -> g_h1
    gemm_fused<true, true, PTR_PARAM, PTR_H1><<<dim3(IDIM / 64, CAP / 128, NE), 256>>>(
        x, HDIM,
        w13, 2 * IDIM, IDIM, (long long)HDIM * 2 * IDIM,
        nullptr, IDIM, (long long)CAP * IDIM,
        CAP, HDIM);
    // routed gemm2: g_h1 @ w2 -> g_y
    gemm_plain<true, PTR_H1, PTR_Y><<<dim3(HDIM / 128, CAP / 128, NE), 256>>>(
        nullptr, IDIM, (long long)CAP * IDIM,
        w2, HDIM, (long long)IDIM * HDIM,
        nullptr, HDIM, (long long)CAP * HDIM,
        CAP, IDIM);
    // shared gemm1: X @ shared_gate_up (fused silu*up) -> g_hs
    gemm_fused<false, false, PTR_PARAM, PTR_HS><<<dim3(ISH / 64, T / 128, 1), 256>>>(
        x, HDIM,
        sgu, 2 * ISH, ISH, 0ll,
        nullptr, ISH, 0ll,
        T, HDIM);
    // shared gemm2: g_hs @ shared_down -> out
    gemm_plain<false, PTR_HS, PTR_PARAM><<<dim3(HDIM / 128, T / 128, 1), 256>>>(
        nullptr, ISH, 0ll,
        sdn, HDIM, 0ll,
        out, HDIM, 0ll,
        T, ISH);
    combine_kernel<<<T, 256>>>(out);
}

// round 5
// speedup vs baseline: 2.3315x; 2.3315x over previous
#include <cuda_runtime.h>
#include <math.h>
#include <stdint.h>

// Problem constants
#define T      512
#define HDIM   2048
#define NE     32
#define TOPK   8
#define IDIM   1408
#define NGRP   8
#define TKG    4
#define CAP    256
#define RSF    2.5f
#define ISH    2816

// SMEM row stride in words for [row][k16] tiles: 16 data + 4 pad (80B, 16B aligned)
#define RS 20

// ---------------- device scratch ----------------
__device__ int   g_topk_ids[T * TOPK];
__device__ float g_topk_w[T * TOPK];
__device__ int   g_assign_slot[T * TOPK];
__device__ int   g_slot_token[NE * CAP];
__device__ int   g_counts[NE];
__device__ float g_h1[NE * CAP * IDIM];
__device__ float g_y [NE * CAP * HDIM];
__device__ float g_hs[T * ISH];

#define PTR_PARAM 0
#define PTR_H1    1
#define PTR_Y     2
#define PTR_HS    3

template <int M>
__device__ __forceinline__ float* resolve(float* p) {
    if constexpr (M == PTR_H1) return g_h1;
    else if constexpr (M == PTR_Y) return g_y;
    else if constexpr (M == PTR_HS) return g_hs;
    else return p;
}

// ---------------- helpers ----------------
__device__ __forceinline__ unsigned f2tf(float f) {
    unsigned r; asm("cvt.rna.tf32.f32 %0, %1;" : "=r"(r) : "f"(f)); return r;
}
__device__ __forceinline__ void mma_tf32(float* c, uint4 a, unsigned b0, unsigned b1) {
    asm("mma.sync.aligned.m16n8k8.row.col.f32.tf32.tf32.f32 "
        "{%0,%1,%2,%3},{%4,%5,%6,%7},{%8,%9},{%0,%1,%2,%3};"
        : "+f"(c[0]), "+f"(c[1]), "+f"(c[2]), "+f"(c[3])
        : "r"(a.x), "r"(a.y), "r"(a.z), "r"(a.w), "r"(b0), "r"(b1));
}
__device__ __forceinline__ uint4 ldsm4(unsigned addr) {
    uint4 r;
    asm volatile("ldmatrix.sync.aligned.m8n8.x4.shared.b16 {%0,%1,%2,%3}, [%4];"
                 : "=r"(r.x), "=r"(r.y), "=r"(r.z), "=r"(r.w) : "r"(addr));
    return r;
}
__device__ __forceinline__ float silu_mul(float g, float u) {
    return (g / (1.f + expf(-g))) * u;
}
__device__ __forceinline__ uint4 cvt4(float4 v) {
    return make_uint4(f2tf(v.x), f2tf(v.y), f2tf(v.z), f2tf(v.w));
}

// ---------------- routing ----------------
__global__ void routing_kernel(const float* __restrict__ x,
                               const float* __restrict__ gw,
                               const float* __restrict__ bias) {
    int t    = blockIdx.x;
    int tid  = threadIdx.x;
    int lane = tid & 31;
    int wid  = tid >> 5;

    __shared__ float part[8][32];
    const float* xr = x + (long long)t * HDIM;
    float acc = 0.f;
    int h0 = wid * (HDIM / 8);
    for (int h = h0; h < h0 + HDIM / 8; ++h)
        acc += xr[h] * gw[h * NE + lane];
    part[wid][lane] = acc;
    __syncthreads();

    if (wid != 0) return;

    float logit = 0.f;
#pragma unroll
    for (int w = 0; w < 8; ++w) logit += part[w][lane];

    float s  = 1.f / (1.f + expf(-logit));
    float sb = s + bias[lane];

    float p   = __shfl_xor_sync(0xffffffffu, sb, 1);
    float hi  = fmaxf(sb, p), lo = fminf(sb, p);
    float hi2 = __shfl_xor_sync(0xffffffffu, hi, 2);
    float lo2 = __shfl_xor_sync(0xffffffffu, lo, 2);
    float gs  = (hi >= hi2) ? hi + fmaxf(hi2, lo) : hi2 + fmaxf(hi, lo2);

    int g = lane >> 2;
    int grank = 0;
#pragma unroll
    for (int g2 = 0; g2 < NGRP; ++g2) {
        float og = __shfl_sync(0xffffffffu, gs, g2 * 4);
        if (og > gs || (og == gs && g2 < g)) ++grank;
    }
    float cand = (grank < TKG) ? sb : -INFINITY;

    float v = cand;
    int   sel_e = 0; float sel_w = 0.f;
#pragma unroll
    for (int k = 0; k < TOPK; ++k) {
        float bv = v; int bi = lane;
#pragma unroll
        for (int off = 16; off; off >>= 1) {
            float ov = __shfl_xor_sync(0xffffffffu, bv, off);
            int   oi = __shfl_xor_sync(0xffffffffu, bi, off);
            if (ov > bv || (ov == bv && oi < bi)) { bv = ov; bi = oi; }
        }
        float ws = __shfl_sync(0xffffffffu, s, bi);
        if (lane == k)  { sel_e = bi; sel_w = ws; }
        if (lane == bi) v = -INFINITY;
    }

    float wv = (lane < TOPK) ? sel_w : 0.f;
#pragma unroll
    for (int off = 16; off; off >>= 1) wv += __shfl_xor_sync(0xffffffffu, wv, off);
    if (lane < TOPK) {
        g_topk_ids[t * TOPK + lane] = sel_e;
        g_topk_w  [t * TOPK + lane] = sel_w / wv * RSF;
    }
}

// ---------------- capacity ranking ----------------
__global__ void rank_kernel() {
    int w    = threadIdx.x >> 5;
    int lane = threadIdx.x & 31;
    int cnt  = 0;
    for (int i0 = 0; i0 < T * TOPK; i0 += 32) {
        int i = i0 + lane;
        int e = g_topk_ids[i];
        bool m = (e == w);
        unsigned mask = __ballot_sync(0xffffffffu, m);
        if (m) {
            int r = cnt + __popc(mask & ((1u << lane) - 1u));
            if (r < CAP) {
                g_assign_slot[i] = w * CAP + r;
                g_slot_token[w * CAP + r] = i >> 3;
            } else {
                g_assign_slot[i] = -1;
            }
        }
        cnt += __popc(mask);
    }
    if (lane == 0) g_counts[w] = min(cnt, CAP);
}

// ============================================================================
// Fused gate/up tf32 GEMM: C = silu(A@Bg)*(A@Bu). Block M=128,N=64.
// 8 warps 4(m) x 2(n); warp tile 32x32. SMEM [row][k] + ldmatrix fragments.
// ============================================================================
template <bool GATHER, bool GROUPED, int AM, int CM>
__global__ void __launch_bounds__(256, 2)
gemm_fused(const float* __restrict__ Ain, int lda,
           const float* __restrict__ B, int ldb, int up_off, long long b_estride,
           float* __restrict__ Cin, int ldc, long long c_estride,
           int M, int Kd) {
    const float* A  = resolve<AM>(const_cast<float*>(Ain));
    float*       Cm = resolve<CM>(Cin);

    const int e    = GROUPED ? blockIdx.z : 0;
    const int Mloc = GROUPED ? g_counts[e] : M;
    const int m0   = blockIdx.y * 128;
    if (m0 >= Mloc) return;
    const int n0   = blockIdx.x * 64;

    const float* Bp = B + (GROUPED ? (long long)e * b_estride : 0ll);
    float*       Cp = Cm + (GROUPED ? (long long)e * c_estride : 0ll);

    __shared__ unsigned As[128][RS];   // A[m][k]
    __shared__ unsigned Bg[64][RS];    // Bgate[n][k] (transposed)
    __shared__ unsigned Bu[64][RS];    // Bup  [n][k]

    const int tid  = threadIdx.x;
    const int lane = tid & 31;
    const int wid  = tid >> 5;
    const int gid  = lane >> 2;
    const int tig  = lane & 3;
    const int mt0  = (wid >> 1) * 2;   // first m16 tile
    const int nt0  = (wid & 1) * 4;    // first n8 tile

    // ---- A staging mapping: rows r0, r0+64; quad k4 ----
    const int r0 = tid >> 2;
    const int k4 = (tid & 3) * 4;
    const int gm0 = m0 + r0, gm1 = m0 + r0 + 64;
    const bool av0 = gm0 < Mloc, av1 = gm1 < Mloc;
    int row0, row1;
    if (GATHER) {
        row0 = av0 ? g_slot_token[e * CAP + gm0] : 0;
        row1 = av1 ? g_slot_token[e * CAP + gm1] : 0;
    } else {
        row0 = av0 ? gm0 : 0;
        row1 = av1 ? gm1 : 0;
    }
    const float* ap0 = A + (long long)row0 * lda + k4;
    const float* ap1 = A + (long long)row1 * lda + k4;

    // ---- B staging mapping: column bn, 8 k-rows starting bkq; half does gate/up ----
    const int bn  = tid & 63;
    const int bkq = ((tid >> 6) & 1) * 8;
    const bool isUp = (tid >> 7) != 0;
    const float* bp = Bp + n0 + bn + (isUp ? up_off : 0);
    unsigned* bdst = isUp ? &Bu[bn][bkq] : &Bg[bn][bkq];

    float accg[2][4][4], accu[2][4][4];
#pragma unroll
    for (int mi = 0; mi < 2; ++mi)
#pragma unroll
        for (int ni = 0; ni < 4; ++ni)
#pragma unroll
            for (int r = 0; r < 4; ++r) { accg[mi][ni][r] = 0.f; accu[mi][ni][r] = 0.f; }

    // ldmatrix lane addressing
    const unsigned aBase = (unsigned)__cvta_generic_to_shared(&As[0][0]);
    const unsigned gBase = (unsigned)__cvta_generic_to_shared(&Bg[0][0]);
    const unsigned uBase = (unsigned)__cvta_generic_to_shared(&Bu[0][0]);
    const int aRow = (lane & 15);
    const int aCol = (lane >> 4) * 4;
    const int bRow = (lane & 7) + ((lane >> 4) * 8);
    const int bCol = ((lane >> 3) & 1) * 4;

    const float4 fz = make_float4(0.f, 0.f, 0.f, 0.f);
    float4 ra0 = av0 ? *(const float4*)(ap0) : fz;
    float4 ra1 = av1 ? *(const float4*)(ap1) : fz;
    float rb[8];
#pragma unroll
    for (int i = 0; i < 8; ++i) rb[i] = bp[(long long)(bkq + i) * ldb];

    for (int k0 = 0; k0 < Kd; k0 += 16) {
        // stage
        *(uint4*)&As[r0][k4]      = cvt4(ra0);
        *(uint4*)&As[r0 + 64][k4] = cvt4(ra1);
        bdst[0] = f2tf(rb[0]); bdst[1] = f2tf(rb[1]); bdst[2] = f2tf(rb[2]); bdst[3] = f2tf(rb[3]);
        bdst[4] = f2tf(rb[4]); bdst[5] = f2tf(rb[5]); bdst[6] = f2tf(rb[6]); bdst[7] = f2tf(rb[7]);
        __syncthreads();

        const bool nxt = (k0 + 16) < Kd;
        if (nxt) {
            ra0 = av0 ? *(const float4*)(ap0 + k0 + 16) : fz;
            ra1 = av1 ? *(const float4*)(ap1 + k0 + 16) : fz;
#pragma unroll
            for (int i = 0; i < 8; ++i) rb[i] = bp[(long long)(k0 + 16 + bkq + i) * ldb];
        }

#pragma unroll
        for (int kt = 0; kt < 16; kt += 8) {
            uint4 af[2];
#pragma unroll
            for (int mi = 0; mi < 2; ++mi)
                af[mi] = ldsm4(aBase + (((mt0 + mi) * 16 + aRow) * RS + kt + aCol) * 4);
            uint4 bg0 = ldsm4(gBase + (((nt0 + 0) * 8 + bRow) * RS + kt + bCol) * 4);
            uint4 bg1 = ldsm4(gBase + (((nt0 + 2) * 8 + bRow) * RS + kt + bCol) * 4);
            uint4 bu0 = ldsm4(uBase + (((nt0 + 0) * 8 + bRow) * RS + kt + bCol) * 4);
            uint4 bu1 = ldsm4(uBase + (((nt0 + 2) * 8 + bRow) * RS + kt + bCol) * 4);
#pragma unroll
            for (int mi = 0; mi < 2; ++mi) {
                mma_tf32(accg[mi][0], af[mi], bg0.x, bg0.y);
                mma_tf32(accg[mi][1], af[mi], bg0.z, bg0.w);
                mma_tf32(accg[mi][2], af[mi], bg1.x, bg1.y);
                mma_tf32(accg[mi][3], af[mi], bg1.z, bg1.w);
                mma_tf32(accu[mi][0], af[mi], bu0.x, bu0.y);
                mma_tf32(accu[mi][1], af[mi], bu0.z, bu0.w);
                mma_tf32(accu[mi][2], af[mi], bu1.x, bu1.y);
                mma_tf32(accu[mi][3], af[mi], bu1.z, bu1.w);
            }
        }
        __syncthreads();
    }

    // epilogue
#pragma unroll
    for (int mi = 0; mi < 2; ++mi) {
        int rA = m0 + (mt0 + mi) * 16 + gid;
        int rB = rA + 8;
#pragma unroll
        for (int ni = 0; ni < 4; ++ni) {
            int c0 = n0 + (nt0 + ni) * 8 + 2 * tig;
            if (rA < Mloc) {
                Cp[(long long)rA * ldc + c0    ] = silu_mul(accg[mi][ni][0], accu[mi][ni][0]);
                Cp[(long long)rA * ldc + c0 + 1] = silu_mul(accg[mi][ni][1], accu[mi][ni][1]);
            }
            if (rB < Mloc) {
                Cp[(long long)rB * ldc + c0    ] = silu_mul(accg[mi][ni][2], accu[mi][ni][2]);
                Cp[(long long)rB * ldc + c0 + 1] = silu_mul(accg[mi][ni][3], accu[mi][ni][3]);
            }
        }
    }
}

// ============================================================================
// Plain tf32 GEMM: C = A @ B. Block M=128,N=128. 8 warps 2(m) x 4(n);
// warp tile 64x32. SMEM [row][k] + ldmatrix fragments.
// ============================================================================
template <bool GROUPED, int AM, int CM>
__global__ void __launch_bounds__(256, 2)
gemm_plain(const float* __restrict__ Ain, int lda, long long a_estride,
           const float* __restrict__ B, int ldb, long long b_estride,
           float* __restrict__ Cin, int ldc, long long c_estride,
           int M, int Kd) {
    const float* A  = resolve<AM>(const_cast<float*>(Ain));
    float*       Cm = resolve<CM>(Cin);

    const int e    = GROUPED ? blockIdx.z : 0;
    const int Mloc = GROUPED ? g_counts[e] : M;
    const int m0   = blockIdx.y * 128;
    if (m0 >= Mloc) return;
    const int n0   = blockIdx.x * 128;

    const float* Bp = B + (GROUPED ? (long long)e * b_estride : 0ll);
    const float* Ap = A + (GROUPED ? (long long)e * a_estride : 0ll);
    float*       Cp = Cm + (GROUPED ? (long long)e * c_estride : 0ll);

    __shared__ unsigned As[128][RS];   // A[m][k]
    __shared__ unsigned Bs[128][RS];   // B[n][k] (transposed)

    const int tid  = threadIdx.x;
    const int lane = tid & 31;
    const int wid  = tid >> 5;
    const int gid  = lane >> 2;
    const int tig  = lane & 3;
    const int mt0  = (wid >> 2) * 4;
    const int nt0  = (wid & 3) * 4;

    const int r0 = tid >> 2;
    const int k4 = (tid & 3) * 4;
    const int gm0 = m0 + r0, gm1 = m0 + r0 + 64;
    const bool av0 = gm0 < Mloc, av1 = gm1 < Mloc;
    const float* ap0 = Ap + (long long)(av0 ? gm0 : 0) * lda + k4;
    const float* ap1 = Ap + (long long)(av1 ? gm1 : 0) * lda + k4;

    const int bn  = tid & 127;
    const int bkq = (tid >> 7) * 8;
    const float* bp = Bp + n0 + bn;
    unsigned* bdst = &Bs[bn][bkq];

    float acc[4][4][4];
#pragma unroll
    for (int mi = 0; mi < 4; ++mi)
#pragma unroll
        for (int ni = 0; ni < 4; ++ni)
#pragma unroll
            for (int r = 0; r < 4; ++r) acc[mi][ni][r] = 0.f;

    const unsigned aBase = (unsigned)__cvta_generic_to_shared(&As[0][0]);
    const unsigned bBase = (unsigned)__cvta_generic_to_shared(&Bs[0][0]);
    const int aRow = (lane & 15);
    const int aCol = (lane >> 4) * 4;
    const int bRow = (lane & 7) + ((lane >> 4) * 8);
    const int bCol = ((lane >> 3) & 1) * 4;

    const float4 fz = make_float4(0.f, 0.f, 0.f, 0.f);
    float4 ra0 = av0 ? *(const float4*)(ap0) : fz;
    float4 ra1 = av1 ? *(const float4*)(ap1) : fz;
    float rb[8];
#pragma unroll
    for (int i = 0; i < 8; ++i) rb[i] = bp[(long long)(bkq + i) * ldb];

    for (int k0 = 0; k0 < Kd; k0 += 16) {
        *(uint4*)&As[r0][k4]      = cvt4(ra0);
        *(uint4*)&As[r0 + 64][k4] = cvt4(ra1);
        bdst[0] = f2tf(rb[0]); bdst[1] = f2tf(rb[1]); bdst[2] = f2tf(rb[2]); bdst[3] = f2tf(rb[3]);
        bdst[4] = f2tf(rb[4]); bdst[5] = f2tf(rb[5]); bdst[6] = f2tf(rb[6]); bdst[7] = f2tf(rb[7]);
        __syncthreads();

        const bool nxt = (k0 + 16) < Kd;
        if (nxt) {
            ra0 = av0 ? *(const float4*)(ap0 + k0 + 16) : fz;
            ra1 = av1 ? *(const float4*)(ap1 + k0 + 16) : fz;
#pragma unroll
            for (int i = 0; i < 8; ++i) rb[i] = bp[(long long)(k0 + 16 + bkq + i) * ldb];
        }

#pragma unroll
        for (int kt = 0; kt < 16; kt += 8) {
            uint4 af[4];
#pragma unroll
            for (int mi = 0; mi < 4; ++mi)
                af[mi] = ldsm4(aBase + (((mt0 + mi) * 16 + aRow) * RS + kt + aCol) * 4);
            uint4 b0 = ldsm4(bBase + (((nt0 + 0) * 8 + bRow) * RS + kt + bCol) * 4);
            uint4 b1 = ldsm4(bBase + (((nt0 + 2) * 8 + bRow) * RS + kt + bCol) * 4);
#pragma unroll
            for (int mi = 0; mi < 4; ++mi) {
                mma_tf32(acc[mi][0], af[mi], b0.x, b0.y);
                mma_tf32(acc[mi][1], af[mi], b0.z, b0.w);
                mma_tf32(acc[mi][2], af[mi], b1.x, b1.y);
                mma_tf32(acc[mi][3], af[mi], b1.z, b1.w);
            }
        }
        __syncthreads();
    }

#pragma unroll
    for (int mi = 0; mi < 4; ++mi) {
        int rA = m0 + (mt0 + mi) * 16 + gid;
        int rB = rA + 8;
#pragma unroll
        for (int ni = 0; ni < 4; ++ni) {
            int c0 = n0 + (nt0 + ni) * 8 + 2 * tig;
            if (rA < Mloc) {
                Cp[(long long)rA * ldc + c0    ] = acc[mi][ni][0];
                Cp[(long long)rA * ldc + c0 + 1] = acc[mi][ni][1];
            }
            if (rB < Mloc) {
                Cp[(long long)rB * ldc + c0    ] = acc[mi][ni][2];
                Cp[(long long)rB * ldc + c0 + 1] = acc[mi][ni][3];
            }
        }
    }
}

// ---------------- combine ----------------
__global__ void combine_kernel(float* __restrict__ out) {
    int t = blockIdx.x;
    __shared__ int   sslot[TOPK];
    __shared__ float sw[TOPK];
    if (threadIdx.x < TOPK) {
        sslot[threadIdx.x] = g_assign_slot[t * TOPK + threadIdx.x];
        sw[threadIdx.x]    = g_topk_w[t * TOPK + threadIdx.x];
    }
    __syncthreads();
    for (int h = threadIdx.x; h < HDIM; h += 256) {
        float acc = out[(long long)t * HDIM + h];
#pragma unroll
        for (int k = 0; k < TOPK; ++k) {
            int sl = sslot[k];
            if (sl >= 0) acc += sw[k] * g_y[(long long)sl * HDIM + h];
        }
        out[(long long)t * HDIM + h] = acc;
    }
}

// ---------------- launch ----------------
extern "C" void kernel_launch(void* const* d_in, const int* in_sizes, int n_in,
                              void* d_out, int out_size) {
    const float* x     = (const float*)d_in[0];
    const float* gw    = (const float*)d_in[2];
    const float* bias  = (const float*)d_in[3];
    const float* w13   = (const float*)d_in[4];
    const float* w2    = (const float*)d_in[5];
    const float* sgu   = (const float*)d_in[6];
    const float* sdn   = (const float*)d_in[7];
    float* out = (float*)d_out;

    routing_kernel<<<T, 256>>>(x, gw, bias);
    rank_kernel<<<1, 1024>>>();
    gemm_fused<true, true, PTR_PARAM, PTR_H1><<<dim3(IDIM / 64, CAP / 128, NE), 256>>>(
        x, HDIM,
        w13, 2 * IDIM, IDIM, (long long)HDIM * 2 * IDIM,
        nullptr, IDIM, (long long)CAP * IDIM,
        CAP, HDIM);
    gemm_plain<true, PTR_H1, PTR_Y><<<dim3(HDIM / 128, CAP / 128, NE), 256>>>(
        nullptr, IDIM, (long long)CAP * IDIM,
        w2, HDIM, (long long)IDIM * HDIM,
        nullptr, HDIM, (long long)CAP * HDIM,
        CAP, IDIM);
    gemm_fused<false, false, PTR_PARAM, PTR_HS><<<dim3(ISH / 64, T / 128, 1), 256>>>(
        x, HDIM,
        sgu, 2 * ISH, ISH, 0ll,
        nullptr, ISH, 0ll,
        T, HDIM);
    gemm_plain<false, PTR_HS, PTR_PARAM><<<dim3(HDIM / 128, T / 128, 1), 256>>>(
        nullptr, ISH, 0ll,
        sdn, HDIM, 0ll,
        out, HDIM, 0ll,
        T, ISH);
    combine_kernel<<<T, 256>>>(out);
}